// round 7
// baseline (speedup 1.0000x reference)
#include <cuda_runtime.h>
#include <cuda_fp16.h>
#include <math.h>

#define NN    512
#define FF    128
#define HH    256
#define MM    256
#define DEGN  8
#define HISTN 10
#define OO    64
#define PPV   2
#define MAXS  (10*NN)     /* 5120 */
#define NB    148         /* k_main grid */
#define TPB   512
#define MAXW  192         /* per-CTA list capacity */
#define RS    8           /* prefetch ring slots (power of 2) */

/* -------- persistent scratch (device globals; no allocation allowed) ------ */
__device__ float g_hist [NN*HISTN*HH];           // node state ring buffers
__device__ float g_msgs [MAXS*MM];               // message produced by each step
__device__ __align__(16) __half g_A_h [HH*HH];   // A = Wq @ Wk^T (fused q->kq)
__device__ __align__(16) __half g_wr_h[HH*HH];   // fp16 Wr_sum
__device__ __align__(16) __half g_wm_h[2*HH*MM]; // fp16 Wm (rows 0..255 = ns, 256..511 = msg)
__device__ float g_bqk  [HH];                    // Wk @ bq
__device__ int   g_node [MAXS];
__device__ int   g_home [NN];
__device__ int   g_count[NN];
__device__ int   g_done_msg[MAXS];

/* ------------------------- sync helpers ---------------------------------- */
__device__ __forceinline__ int ld_acq(const int* p) {
    int v;
    asm volatile("ld.acquire.gpu.global.b32 %0, [%1];" : "=r"(v) : "l"(p) : "memory");
    return v;
}
__device__ __forceinline__ void st_rel(int* p, int v) {
    asm volatile("st.release.gpu.global.b32 [%0], %1;" :: "l"(p), "r"(v) : "memory");
}
#define BARH(id) asm volatile("bar.sync %0, 256;" :: "r"(id) : "memory")

/* ---------------- K1: encode xa -> hist slot0, zero flags ----------------- */
__global__ void k_encode(const float* __restrict__ xa, const float* __restrict__ We,
                         const float* __restrict__ be)
{
    __shared__ float sx[FF];
    int n = blockIdx.x, t = threadIdx.x;
    if (t < FF) sx[t] = xa[n*FF + t];
    __syncthreads();
    float acc = be[t];
    #pragma unroll 4
    for (int f = 0; f < FF; ++f) acc += sx[f] * We[f*HH + t];
    g_hist[((size_t)n*HISTN + 0)*HH + t] = acc;
    if (t < HISTN) g_done_msg[n*HISTN + t] = 0;   // 512*10 == MAXS
}

/* ---------------- K2: Wr_sum (fp16) --------------------------------------- */
__global__ void k_wrsum(const float* __restrict__ Wr)
{
    int i = blockIdx.x, t = threadIdx.x;
    float s = Wr[i*HH + t] + Wr[(HH + i)*HH + t]
            + Wr[(2*HH + i)*HH + t] + Wr[(3*HH + i)*HH + t];
    g_wr_h[i*HH + t] = __float2half(s);
}

/* ---------------- K2b: Wm -> fp16 ----------------------------------------- */
__global__ void k_wmh(const float* __restrict__ Wm)
{
    int b = blockIdx.x, t = threadIdx.x;
    g_wm_h[b*MM + t] = __float2half(Wm[(size_t)b*MM + t]);
}

/* ---------------- K2c: A = Wq @ Wk^T  (fp16 out) -------------------------- */
__global__ void k_prec(const float* __restrict__ Wq, const float* __restrict__ Wk)
{
    __shared__ float a[32][33], bt[32][33];
    int tx = threadIdx.x, ty = threadIdx.y;
    int m0 = blockIdx.y*32, i0 = blockIdx.x*32;
    float acc = 0.f;
    for (int kt = 0; kt < HH; kt += 32) {
        a [ty][tx] = Wq[(m0+ty)*HH + kt + tx];
        bt[tx][ty] = Wk[(i0+ty)*HH + kt + tx];   // bt[h][i]
        __syncthreads();
        #pragma unroll
        for (int k = 0; k < 32; ++k) acc += a[ty][k]*bt[k][tx];
        __syncthreads();
    }
    g_A_h[(m0+ty)*HH + i0 + tx] = __float2half(acc);
}

/* ---------------- K2d: bqk = Wk @ bq -------------------------------------- */
__global__ void k_bqk(const float* __restrict__ Wk, const float* __restrict__ bq)
{
    int w = threadIdx.x >> 5, l = threadIdx.x & 31;
    int r = blockIdx.x*8 + w;
    float p = 0.f;
    #pragma unroll
    for (int k = 0; k < 8; ++k) { int h = l + k*32; p += Wk[r*HH + h]*bq[h]; }
    #pragma unroll
    for (int o = 16; o > 0; o >>= 1) p += __shfl_down_sync(0xffffffffu, p, o);
    if (l == 0) g_bqk[r] = p;
}

/* ------- K3: sequence, visit totals, homes -------------------------------- */
__global__ void k_graph(const int* __restrict__ neighbors, const int* __restrict__ ns_ptr)
{
    __shared__ int sn[MAXS];   // 20 KB
    __shared__ int T[NN], P[NN];
    int t = threadIdx.x;
    int S = *ns_ptr;
    for (int e = t; e < S && e < MAXS; e += TPB) sn[e] = e;
    __syncthreads();
    int known = S;
    while (known < MAXS) {
        long long nx = (long long)S + 8LL*(long long)known;
        int next = (nx > MAXS) ? MAXS : (int)nx;
        for (int e = known + t; e < next; e += TPB) {
            int src = (e - S) >> 3;
            sn[e] = neighbors[sn[src]*DEGN + ((e - S) & 7)];
        }
        __syncthreads();
        known = next;
    }
    T[t] = 0;
    __syncthreads();
    for (int e = t; e < MAXS; e += TPB) atomicAdd(&T[sn[e]], 1);
    __syncthreads();
    P[t] = T[t];
    __syncthreads();
    for (int o = 1; o < NN; o <<= 1) {            // inclusive scan over node ids
        int v = (t >= o) ? P[t-o] : 0;
        __syncthreads();
        P[t] += v;
        __syncthreads();
    }
    {
        int excl = P[t] - T[t];
        g_home[t]  = (int)(((long long)excl * NB) / MAXS);
        g_count[t] = 1 + T[t];
    }
    for (int e = t; e < MAXS; e += TPB) g_node[e] = sn[e];
}

/* ------- K4: persistent warp-specialized dataflow processor ----------------
   warps 0-7  (tid 0..255)   = chain engine (attention + Wr + Wm1 + publish)
   warps 8-15 (tid 256..511) = prefetch engine (kq = msg@A, w2 = msg@Wm2)    */
__global__ void __launch_bounds__(TPB)
k_main(const float* __restrict__ first_message,
       const float* __restrict__ br, const float* __restrict__ bm,
       const int*   __restrict__ ns_ptr)
{
    __shared__ float s_kq[RS][HH];          // 8 KB  ring: kq per position
    __shared__ float s_w2[RS][HH];          // 8 KB  ring: msg@Wm2+bm per position
    __shared__ float s_pm[MM];              // 1 KB  prefetch msg staging
    __shared__ float2 s_pc[2][128];         // 2 KB  chain matvec partials
    __shared__ float2 s_pp[2][128];         // 2 KB  prefetch matvec partials
    __shared__ float s_vals[HH], s_ns[HH];  // 2 KB
    __shared__ float s_logit[16], s_attn[HISTN];
    __shared__ int   s_cnt[NN];             // 2 KB  per-node visit counts
    __shared__ int   s_scan[TPB];           // 2 KB
    __shared__ int   s_lstep[MAXW], s_lnode[MAXW];
    __shared__ int   s_ready[RS];
    __shared__ int   s_cons;
    __shared__ int   s_L;

    const int tid = threadIdx.x;
    const int cta = blockIdx.x;
    const int S   = *ns_ptr;

    /* ---- build this CTA's ordered step list (stable compaction) ---- */
    {
        int e0 = tid*10, cl = 0;
        #pragma unroll
        for (int k = 0; k < 10; ++k)
            if (g_home[g_node[e0+k]] == cta) ++cl;
        s_scan[tid] = cl;
        __syncthreads();
        for (int o = 1; o < TPB; o <<= 1) {
            int v = (tid >= o) ? s_scan[tid-o] : 0;
            __syncthreads();
            s_scan[tid] += v;
            __syncthreads();
        }
        int base = s_scan[tid] - cl;
        #pragma unroll
        for (int k = 0; k < 10; ++k) {
            int e = e0 + k, nd = g_node[e];
            if (g_home[nd] == cta) { s_lstep[base] = e; s_lnode[base] = nd; ++base; }
        }
        if (tid == TPB-1) { s_L = s_scan[TPB-1]; s_cons = 0; }
        if (tid < RS) s_ready[tid] = 0;
        for (int n = tid; n < NN; n += TPB) s_cnt[n] = 1;
        __syncthreads();
    }
    const int L = s_L;

    if (tid < 256) {
        /* =================== CHAIN ENGINE =================== */
        const int wid = tid >> 5, lid = tid & 31;
        const int g = tid >> 7, c = tid & 127;
        for (int p = 0; p < L; ++p) {
            const int slot = p & (RS-1);
            while (*(volatile int*)&s_ready[slot] != p+1) {}
            __threadfence_block();
            const int nd   = s_lnode[p];
            const int cnt  = s_cnt[nd];
            const int nv   = (cnt < HISTN) ? cnt : HISTN;
            const int hsl  = cnt % HISTN;
            /* logits over history slots */
            #pragma unroll
            for (int pass = 0; pass < 2; ++pass) {
                int sl = wid + pass*8;
                if (sl < nv) {
                    const float* hp = g_hist + ((size_t)nd*HISTN + sl)*HH;
                    float pr = 0.f;
                    #pragma unroll
                    for (int k = 0; k < 8; ++k) { int h = lid + k*32; pr += hp[h]*s_kq[slot][h]; }
                    #pragma unroll
                    for (int o = 16; o > 0; o >>= 1) pr += __shfl_down_sync(0xffffffffu, pr, o);
                    if (lid == 0) s_logit[sl] = pr * 0.0625f;
                }
            }
            BARH(1);
            if (tid == 0) {
                float m = -1e30f;
                for (int k = 0; k < nv; ++k) m = fmaxf(m, s_logit[k]);
                float sum = 0.f;
                for (int k = 0; k < nv; ++k) { float e = __expf(s_logit[k]-m); s_attn[k]=e; sum+=e; }
                float inv = 1.f / sum;
                for (int k = 0; k < nv; ++k) s_attn[k] *= inv;
            }
            BARH(1);
            /* values */
            {
                float v = 0.f;
                const float* hp = g_hist + (size_t)nd*HISTN*HH + tid;
                #pragma unroll 2
                for (int k = 0; k < nv; ++k) v += s_attn[k]*hp[k*HH];
                s_vals[tid] = v;
            }
            BARH(1);
            /* ns = vals @ Wr_sum + br */
            {
                const __half2* W = (const __half2*)g_wr_h;
                float2 a = make_float2(0.f, 0.f);
                const int i0 = g*128;
                #pragma unroll 8
                for (int i = i0; i < i0+128; ++i) {
                    float x = s_vals[i];
                    float2 w = __half22float2(W[i*128 + c]);
                    a.x += x*w.x; a.y += x*w.y;
                }
                s_pc[g][c] = a;
            }
            BARH(1);
            if (tid < 128) {
                float2 b2 = ((const float2*)br)[tid];
                float2 r; r.x = s_pc[0][tid].x + s_pc[1][tid].x + b2.x;
                          r.y = s_pc[0][tid].y + s_pc[1][tid].y + b2.y;
                ((float2*)s_ns)[tid] = r;
                ((float2*)(g_hist + ((size_t)nd*HISTN + hsl)*HH))[tid] = r;
            }
            if (tid == 255) s_cnt[nd] = cnt + 1;
            BARH(1);
            /* out = ns @ Wm1 + w2 ; publish message */
            {
                const __half2* W = (const __half2*)g_wm_h;   /* rows 0..255 */
                float2 a = make_float2(0.f, 0.f);
                const int i0 = g*128;
                #pragma unroll 8
                for (int i = i0; i < i0+128; ++i) {
                    float x = s_ns[i];
                    float2 w = __half22float2(W[i*128 + c]);
                    a.x += x*w.x; a.y += x*w.y;
                }
                s_pc[g][c] = a;
            }
            BARH(1);
            {
                const int s = s_lstep[p];
                if (tid < 128) {
                    float2 w2 = ((float2*)s_w2[slot])[tid];
                    float2 r; r.x = s_pc[0][tid].x + s_pc[1][tid].x + w2.x;
                              r.y = s_pc[0][tid].y + s_pc[1][tid].y + w2.y;
                    ((float2*)(g_msgs + (size_t)s*MM))[tid] = r;
                }
                BARH(1);
                if (tid == 0) {
                    __threadfence();
                    st_rel(&g_done_msg[s], 1);
                    *(volatile int*)&s_cons = p + 1;
                }
            }
        }
    } else {
        /* =================== PREFETCH ENGINE =================== */
        const int pt = tid & 255;
        const int g = pt >> 7, c = pt & 127;
        for (int p = 0; p < L; ++p) {
            const int slot = p & (RS-1);
            const int s  = s_lstep[p];
            const int sr = (s >= S) ? ((s - S) >> 3) : -1;
            if (pt == 0) {
                while (p >= *(volatile int*)&s_cons + RS) {}      /* ring space */
                if (sr >= 0) { while (ld_acq(&g_done_msg[sr]) == 0) {} }
            }
            BARH(2);
            s_pm[pt] = (sr < 0)
                ? __ldg(first_message + (size_t)s*MM + pt)
                : __ldcg(g_msgs + (size_t)sr*MM + pt);
            BARH(2);
            /* kq = msg @ A + bqk */
            {
                const __half2* W = (const __half2*)g_A_h;
                float2 a = make_float2(0.f, 0.f);
                const int i0 = g*128;
                #pragma unroll 8
                for (int i = i0; i < i0+128; ++i) {
                    float x = s_pm[i];
                    float2 w = __half22float2(W[i*128 + c]);
                    a.x += x*w.x; a.y += x*w.y;
                }
                s_pp[g][c] = a;
            }
            BARH(2);
            if (pt < 128) {
                float2 b2 = ((const float2*)g_bqk)[pt];
                float2 r; r.x = s_pp[0][pt].x + s_pp[1][pt].x + b2.x;
                          r.y = s_pp[0][pt].y + s_pp[1][pt].y + b2.y;
                ((float2*)s_kq[slot])[pt] = r;
            }
            BARH(2);
            /* w2 = msg @ Wm2 + bm */
            {
                const __half2* W = (const __half2*)(g_wm_h + (size_t)HH*MM);
                float2 a = make_float2(0.f, 0.f);
                const int i0 = g*128;
                #pragma unroll 8
                for (int i = i0; i < i0+128; ++i) {
                    float x = s_pm[i];
                    float2 w = __half22float2(W[i*128 + c]);
                    a.x += x*w.x; a.y += x*w.y;
                }
                s_pp[g][c] = a;
            }
            BARH(2);
            if (pt < 128) {
                float2 b2 = ((const float2*)bm)[pt];
                float2 r; r.x = s_pp[0][pt].x + s_pp[1][pt].x + b2.x;
                          r.y = s_pp[0][pt].y + s_pp[1][pt].y + b2.y;
                ((float2*)s_w2[slot])[pt] = r;
            }
            BARH(2);
            if (pt == 0) {
                __threadfence_block();
                *(volatile int*)&s_ready[slot] = p + 1;
            }
        }
    }
}

/* ---------------- K5: decoder + log_softmax ------------------------------- */
__global__ void k_out(const float* __restrict__ Wd, const float* __restrict__ bd,
                      float* __restrict__ out)
{
    __shared__ float s_fin[HH];
    __shared__ float s_log[PPV*OO];
    int n = blockIdx.x, t = threadIdx.x;     /* 128 threads */
    int cnt  = g_count[n];
    int slot = (cnt - 1) % HISTN;
    s_fin[t]       = g_hist[((size_t)n*HISTN + slot)*HH + t];
    s_fin[t + 128] = g_hist[((size_t)n*HISTN + slot)*HH + t + 128];
    __syncthreads();
    int p = t >> 6, o = t & 63;
    float acc = bd[p*OO + o];
    #pragma unroll 4
    for (int h = 0; h < HH; ++h) acc += s_fin[h]*Wd[((size_t)p*HH + h)*OO + o];
    s_log[t] = acc;
    __syncthreads();
    float m = -1e30f;
    for (int k = 0; k < OO; ++k) m = fmaxf(m, s_log[p*OO + k]);
    float sum = 0.f;
    for (int k = 0; k < OO; ++k) sum += expf(s_log[p*OO + k] - m);
    out[((size_t)p*NN + n)*OO + o] = acc - m - logf(sum);
}

/* -------------------------------------------------------------------------- */
extern "C" void kernel_launch(void* const* d_in, const int* in_sizes, int n_in,
                              void* d_out, int out_size)
{
    const float* xa  = (const float*)d_in[0];
    const int*   nbr = (const int*)  d_in[1];
    const float* fm  = (const float*)d_in[2];
    const float* We  = (const float*)d_in[3];
    const float* be  = (const float*)d_in[4];
    const float* Wq  = (const float*)d_in[5];
    const float* bq  = (const float*)d_in[6];
    const float* Wk  = (const float*)d_in[7];
    /* d_in[8] = bk cancels in softmax */
    const float* Wr  = (const float*)d_in[9];
    const float* br  = (const float*)d_in[10];
    const float* Wm  = (const float*)d_in[11];
    const float* bm  = (const float*)d_in[12];
    const float* Wd  = (const float*)d_in[13];
    const float* bd  = (const float*)d_in[14];
    const int*   nS  = (const int*)  d_in[15];

    k_encode<<<NN, HH>>>(xa, We, be);
    k_wrsum <<<HH, HH>>>(Wr);
    k_wmh   <<<2*HH, MM>>>(Wm);
    {
        dim3 g(8, 8), b(32, 32);
        k_prec<<<g, b>>>(Wq, Wk);
    }
    k_bqk   <<<8, 256>>>(Wk, bq);
    k_graph <<<1, TPB>>>(nbr, nS);
    k_main  <<<NB, TPB>>>(fm, br, bm, nS);
    k_out   <<<NN, 128>>>(Wd, bd, (float*)d_out);
}

// round 8
// speedup vs baseline: 2.0189x; 2.0189x over previous
#include <cuda_runtime.h>
#include <cuda_fp16.h>
#include <math.h>

#define NN    512
#define FF    128
#define HH    256
#define MM    256
#define DEGN  8
#define HISTN 10
#define OO    64
#define PPV   2
#define MAXS  (10*NN)     /* 5120 */
#define NB    148         /* k_main grid */
#define TPB   512
#define CHB   4           /* chunk: 1 head (fast path) + up to 3 batched */
#define MAXW  192         /* per-CTA list capacity */

/* -------- persistent scratch (device globals; no allocation allowed) ------ */
__device__ float g_hist [NN*HISTN*HH];           // node state ring buffers
__device__ float g_msgs [MAXS*MM];               // message produced by each step
__device__ __align__(16) __half g_A_h [HH*HH];   // A = Wq @ Wk^T (fused q->kq)
__device__ __align__(16) __half g_wr_h[HH*HH];   // fp16 Wr_sum
__device__ __align__(16) __half g_wm_h[2*HH*MM]; // fp16 Wm (rows 0..255 = ns, 256..511 = msg)
__device__ float g_bqk  [HH];                    // Wk @ bq
__device__ int   g_node [MAXS];
__device__ int   g_home [NN];
__device__ int   g_count[NN];
__device__ int   g_done_msg[MAXS];

/* ------------------------- sync helpers ---------------------------------- */
__device__ __forceinline__ int ld_acq(const int* p) {
    int v;
    asm volatile("ld.acquire.gpu.global.b32 %0, [%1];" : "=r"(v) : "l"(p) : "memory");
    return v;
}
__device__ __forceinline__ void st_rel(int* p, int v) {
    asm volatile("st.release.gpu.global.b32 [%0], %1;" :: "l"(p), "r"(v) : "memory");
}

/* ---------------- K1: encode xa -> hist slot0, zero flags ----------------- */
__global__ void k_encode(const float* __restrict__ xa, const float* __restrict__ We,
                         const float* __restrict__ be)
{
    __shared__ float sx[FF];
    int n = blockIdx.x, t = threadIdx.x;
    if (t < FF) sx[t] = xa[n*FF + t];
    __syncthreads();
    float acc = be[t];
    #pragma unroll 4
    for (int f = 0; f < FF; ++f) acc += sx[f] * We[f*HH + t];
    g_hist[((size_t)n*HISTN + 0)*HH + t] = acc;
    if (t < HISTN) g_done_msg[n*HISTN + t] = 0;   // 512*10 == MAXS
}

/* ---------------- K2: Wr_sum (fp16) --------------------------------------- */
__global__ void k_wrsum(const float* __restrict__ Wr)
{
    int i = blockIdx.x, t = threadIdx.x;
    float s = Wr[i*HH + t] + Wr[(HH + i)*HH + t]
            + Wr[(2*HH + i)*HH + t] + Wr[(3*HH + i)*HH + t];
    g_wr_h[i*HH + t] = __float2half(s);
}

/* ---------------- K2b: Wm -> fp16 ----------------------------------------- */
__global__ void k_wmh(const float* __restrict__ Wm)
{
    int b = blockIdx.x, t = threadIdx.x;
    g_wm_h[b*MM + t] = __float2half(Wm[(size_t)b*MM + t]);
}

/* ---------------- K2c: A = Wq @ Wk^T  (fp16 out) -------------------------- */
__global__ void k_prec(const float* __restrict__ Wq, const float* __restrict__ Wk)
{
    __shared__ float a[32][33], bt[32][33];
    int tx = threadIdx.x, ty = threadIdx.y;
    int m0 = blockIdx.y*32, i0 = blockIdx.x*32;
    float acc = 0.f;
    for (int kt = 0; kt < HH; kt += 32) {
        a [ty][tx] = Wq[(m0+ty)*HH + kt + tx];
        bt[tx][ty] = Wk[(i0+ty)*HH + kt + tx];   // bt[h][i]
        __syncthreads();
        #pragma unroll
        for (int k = 0; k < 32; ++k) acc += a[ty][k]*bt[k][tx];
        __syncthreads();
    }
    g_A_h[(m0+ty)*HH + i0 + tx] = __float2half(acc);
}

/* ---------------- K2d: bqk = Wk @ bq -------------------------------------- */
__global__ void k_bqk(const float* __restrict__ Wk, const float* __restrict__ bq)
{
    int w = threadIdx.x >> 5, l = threadIdx.x & 31;
    int r = blockIdx.x*8 + w;
    float p = 0.f;
    #pragma unroll
    for (int k = 0; k < 8; ++k) { int h = l + k*32; p += Wk[r*HH + h]*bq[h]; }
    #pragma unroll
    for (int o = 16; o > 0; o >>= 1) p += __shfl_down_sync(0xffffffffu, p, o);
    if (l == 0) g_bqk[r] = p;
}

/* ------- K3: sequence, visit totals, homes -------------------------------- */
__global__ void k_graph(const int* __restrict__ neighbors, const int* __restrict__ ns_ptr)
{
    __shared__ int sn[MAXS];   // 20 KB
    __shared__ int T[NN], P[NN];
    int t = threadIdx.x;
    int S = *ns_ptr;
    for (int e = t; e < S && e < MAXS; e += TPB) sn[e] = e;
    __syncthreads();
    int known = S;
    while (known < MAXS) {
        long long nx = (long long)S + 8LL*(long long)known;
        int next = (nx > MAXS) ? MAXS : (int)nx;
        for (int e = known + t; e < next; e += TPB) {
            int src = (e - S) >> 3;
            sn[e] = neighbors[sn[src]*DEGN + ((e - S) & 7)];
        }
        __syncthreads();
        known = next;
    }
    T[t] = 0;
    __syncthreads();
    for (int e = t; e < MAXS; e += TPB) atomicAdd(&T[sn[e]], 1);
    __syncthreads();
    P[t] = T[t];
    __syncthreads();
    for (int o = 1; o < NN; o <<= 1) {            // inclusive scan over node ids
        int v = (t >= o) ? P[t-o] : 0;
        __syncthreads();
        P[t] += v;
        __syncthreads();
    }
    {
        int excl = P[t] - T[t];
        g_home[t]  = (int)(((long long)excl * NB) / MAXS);
        g_count[t] = 1 + T[t];
    }
    for (int e = t; e < MAXS; e += TPB) g_node[e] = sn[e];
}

/* ---------------- K4: persistent in-order processor, early head publish ---- */
__global__ void __launch_bounds__(TPB)
k_main(const float* __restrict__ first_message,
       const float* __restrict__ br, const float* __restrict__ bm,
       const int*   __restrict__ ns_ptr)
{
    __shared__ float s_msg[CHB][MM];        // 4 KB
    __shared__ float s_kq [CHB][HH];        // 4 KB
    __shared__ float s_ns [CHB][HH];        // 4 KB
    __shared__ float2 s_part[CHB*4][128];   // 16 KB
    __shared__ float s_vals[HH];            // 1 KB
    __shared__ float s_logit[16], s_attn[HISTN];
    __shared__ int   s_cnt[NN];             // 2 KB
    __shared__ int   s_scan[TPB];           // 2 KB
    __shared__ int   s_lstep[MAXW], s_lnode[MAXW];
    __shared__ int   s_cs[CHB], s_cn[CHB];
    __shared__ int   s_B, s_L;

    const int tid = threadIdx.x;
    const int cta = blockIdx.x;
    const int S   = *ns_ptr;
    const int g2  = tid >> 7;       /* 4 groups of 128 */
    const int c   = tid & 127;      /* half2 column */
    const int wid = tid >> 5, lid = tid & 31;

    /* ---- build this CTA's ordered step list (stable compaction) ---- */
    {
        int e0 = tid*10, cl = 0;
        #pragma unroll
        for (int k = 0; k < 10; ++k)
            if (g_home[g_node[e0+k]] == cta) ++cl;
        s_scan[tid] = cl;
        __syncthreads();
        for (int o = 1; o < TPB; o <<= 1) {
            int v = (tid >= o) ? s_scan[tid-o] : 0;
            __syncthreads();
            s_scan[tid] += v;
            __syncthreads();
        }
        int base = s_scan[tid] - cl;
        #pragma unroll
        for (int k = 0; k < 10; ++k) {
            int e = e0 + k, nd = g_node[e];
            if (g_home[nd] == cta) { s_lstep[base] = e; s_lnode[base] = nd; ++base; }
        }
        if (tid == TPB-1) s_L = s_scan[TPB-1];
        for (int n = tid; n < NN; n += TPB) s_cnt[n] = 1;
        __syncthreads();
    }
    const int L = s_L;

    int pos = 0;
    while (pos < L) {
        /* ---- chunk: block on head, extend with already-ready steps ---- */
        if (tid == 0) {
            int s0 = s_lstep[pos];
            if (s0 >= S) { int sr = (s0-S) >> 3; while (ld_acq(&g_done_msg[sr]) == 0) {} }
            s_cs[0] = s0; s_cn[0] = s_lnode[pos];
            int B = 1, p = pos + 1;
            while (B < CHB && p < L) {
                int s = s_lstep[p];
                if (s >= S) {
                    int sr = (s-S) >> 3;
                    if (ld_acq(&g_done_msg[sr]) == 0) break;
                }
                s_cs[B] = s; s_cn[B] = s_lnode[p]; ++B; ++p;
            }
            s_B = B;
        }
        __syncthreads();
        const int B = s_B;

        /* ---- load all chunk messages ---- */
        for (int b = tid >> 8; b < B; b += 2) {
            int cc = tid & 255;
            int s = s_cs[b];
            s_msg[b][cc] = (s < S)
                ? __ldg(first_message + (size_t)s*MM + cc)
                : __ldcg(g_msgs + (size_t)((s - S) >> 3)*MM + cc);
        }
        __syncthreads();

        /* ================= HEAD FAST PATH (step 0, publish early) ========= */
        {
            /* kq0 = msg0 @ A + bqk : 4-way split over 256 rows */
            {
                const __half2* W = (const __half2*)g_A_h;
                float2 a = make_float2(0.f, 0.f);
                const int i0 = g2*64;
                #pragma unroll 8
                for (int i = i0; i < i0+64; ++i) {
                    float x = s_msg[0][i];
                    float2 w = __half22float2(W[i*128 + c]);
                    a.x += x*w.x; a.y += x*w.y;
                }
                s_part[g2][c] = a;
            }
            __syncthreads();
            if (tid < 128) {
                float2 b2 = ((const float2*)g_bqk)[tid];
                float2 r;
                r.x = s_part[0][tid].x + s_part[1][tid].x + s_part[2][tid].x + s_part[3][tid].x + b2.x;
                r.y = s_part[0][tid].y + s_part[1][tid].y + s_part[2][tid].y + s_part[3][tid].y + b2.y;
                ((float2*)s_kq[0])[tid] = r;
            }
            __syncthreads();

            const int nd   = s_cn[0];
            const int cnt  = s_cnt[nd];
            const int nv   = (cnt < HISTN) ? cnt : HISTN;
            const int hsl  = cnt % HISTN;
            /* logits */
            if (wid < nv) {
                const float* hp = g_hist + ((size_t)nd*HISTN + wid)*HH;
                float pr = 0.f;
                #pragma unroll
                for (int k = 0; k < 8; ++k) { int h = lid + k*32; pr += hp[h]*s_kq[0][h]; }
                #pragma unroll
                for (int o = 16; o > 0; o >>= 1) pr += __shfl_down_sync(0xffffffffu, pr, o);
                if (lid == 0) s_logit[wid] = pr * 0.0625f;
            }
            __syncthreads();
            if (tid == 0) {
                float m = -1e30f;
                for (int k = 0; k < nv; ++k) m = fmaxf(m, s_logit[k]);
                float sum = 0.f;
                for (int k = 0; k < nv; ++k) { float e = __expf(s_logit[k]-m); s_attn[k]=e; sum+=e; }
                float inv = 1.f / sum;
                for (int k = 0; k < nv; ++k) s_attn[k] *= inv;
            }
            __syncthreads();
            if (tid < HH) {
                float v = 0.f;
                const float* hp = g_hist + (size_t)nd*HISTN*HH + tid;
                #pragma unroll 2
                for (int k = 0; k < nv; ++k) v += s_attn[k]*hp[k*HH];
                s_vals[tid] = v;
            }
            __syncthreads();
            /* ns0 = vals @ Wr + br */
            {
                const __half2* W = (const __half2*)g_wr_h;
                float2 a = make_float2(0.f, 0.f);
                const int i0 = g2*64;
                #pragma unroll 8
                for (int i = i0; i < i0+64; ++i) {
                    float x = s_vals[i];
                    float2 w = __half22float2(W[i*128 + c]);
                    a.x += x*w.x; a.y += x*w.y;
                }
                s_part[g2][c] = a;
            }
            __syncthreads();
            if (tid < 128) {
                float2 b2 = ((const float2*)br)[tid];
                float2 r;
                r.x = s_part[0][tid].x + s_part[1][tid].x + s_part[2][tid].x + s_part[3][tid].x + b2.x;
                r.y = s_part[0][tid].y + s_part[1][tid].y + s_part[2][tid].y + s_part[3][tid].y + b2.y;
                ((float2*)s_ns[0])[tid] = r;
                ((float2*)(g_hist + ((size_t)nd*HISTN + hsl)*HH))[tid] = r;
            }
            if (tid == TPB-1) s_cnt[nd] = cnt + 1;
            __syncthreads();
            /* out0 = [ns0,msg0] @ Wm + bm : 4 groups x 128 rows */
            {
                const __half2* W = (const __half2*)g_wm_h;
                const float* xs = (g2 < 2) ? (s_ns[0] + g2*128) : (s_msg[0] + (g2-2)*128);
                float2 a = make_float2(0.f, 0.f);
                const int r0 = g2*128;
                #pragma unroll 8
                for (int i = 0; i < 128; ++i) {
                    float x = xs[i];
                    float2 w = __half22float2(W[(r0+i)*128 + c]);
                    a.x += x*w.x; a.y += x*w.y;
                }
                s_part[g2][c] = a;
            }
            __syncthreads();
            if (tid < 128) {
                float2 b2 = ((const float2*)bm)[tid];
                float2 r;
                r.x = s_part[0][tid].x + s_part[1][tid].x + s_part[2][tid].x + s_part[3][tid].x + b2.x;
                r.y = s_part[0][tid].y + s_part[1][tid].y + s_part[2][tid].y + s_part[3][tid].y + b2.y;
                ((float2*)(g_msgs + (size_t)s_cs[0]*MM))[tid] = r;
            }
            __syncthreads();
            if (tid == 0) {
                __threadfence();
                st_rel(&g_done_msg[s_cs[0]], 1);   /* EARLY publish of the head */
            }
        }

        /* ================= BATCH: steps 1..B-1 ============================ */
        if (B > 1) {
            /* batched kq */
            {
                const __half2* W = (const __half2*)g_A_h;
                float2 acc[CHB-1];
                #pragma unroll
                for (int b = 0; b < CHB-1; ++b) acc[b] = make_float2(0.f, 0.f);
                const int i0 = g2*64;
                #pragma unroll 4
                for (int i = i0; i < i0+64; ++i) {
                    float2 w = __half22float2(W[i*128 + c]);
                    #pragma unroll
                    for (int b = 0; b < CHB-1; ++b) {
                        float x = s_msg[b+1][i];
                        acc[b].x += x*w.x; acc[b].y += x*w.y;
                    }
                }
                #pragma unroll
                for (int b = 0; b < CHB-1; ++b) s_part[b*4 + g2][c] = acc[b];
            }
            __syncthreads();
            if (tid < 128) {
                float2 b2 = ((const float2*)g_bqk)[tid];
                for (int b = 1; b < B; ++b) {
                    float2 r;
                    r.x = s_part[(b-1)*4+0][tid].x + s_part[(b-1)*4+1][tid].x
                        + s_part[(b-1)*4+2][tid].x + s_part[(b-1)*4+3][tid].x + b2.x;
                    r.y = s_part[(b-1)*4+0][tid].y + s_part[(b-1)*4+1][tid].y
                        + s_part[(b-1)*4+2][tid].y + s_part[(b-1)*4+3][tid].y + b2.y;
                    ((float2*)s_kq[b])[tid] = r;
                }
            }
            __syncthreads();

            /* serial attention + Wr per step */
            for (int j = 1; j < B; ++j) {
                const int nd   = s_cn[j];
                const int cnt  = s_cnt[nd];
                const int nv   = (cnt < HISTN) ? cnt : HISTN;
                const int hsl  = cnt % HISTN;
                if (wid < nv) {
                    const float* hp = g_hist + ((size_t)nd*HISTN + wid)*HH;
                    float pr = 0.f;
                    #pragma unroll
                    for (int k = 0; k < 8; ++k) { int h = lid + k*32; pr += hp[h]*s_kq[j][h]; }
                    #pragma unroll
                    for (int o = 16; o > 0; o >>= 1) pr += __shfl_down_sync(0xffffffffu, pr, o);
                    if (lid == 0) s_logit[wid] = pr * 0.0625f;
                }
                __syncthreads();
                if (tid == 0) {
                    float m = -1e30f;
                    for (int k = 0; k < nv; ++k) m = fmaxf(m, s_logit[k]);
                    float sum = 0.f;
                    for (int k = 0; k < nv; ++k) { float e = __expf(s_logit[k]-m); s_attn[k]=e; sum+=e; }
                    float inv = 1.f / sum;
                    for (int k = 0; k < nv; ++k) s_attn[k] *= inv;
                }
                __syncthreads();
                if (tid < HH) {
                    float v = 0.f;
                    const float* hp = g_hist + (size_t)nd*HISTN*HH + tid;
                    #pragma unroll 2
                    for (int k = 0; k < nv; ++k) v += s_attn[k]*hp[k*HH];
                    s_vals[tid] = v;
                }
                __syncthreads();
                {
                    const __half2* W = (const __half2*)g_wr_h;
                    float2 a = make_float2(0.f, 0.f);
                    const int i0 = g2*64;
                    #pragma unroll 8
                    for (int i = i0; i < i0+64; ++i) {
                        float x = s_vals[i];
                        float2 w = __half22float2(W[i*128 + c]);
                        a.x += x*w.x; a.y += x*w.y;
                    }
                    s_part[g2][c] = a;
                }
                __syncthreads();
                if (tid < 128) {
                    float2 b2 = ((const float2*)br)[tid];
                    float2 r;
                    r.x = s_part[0][tid].x + s_part[1][tid].x + s_part[2][tid].x + s_part[3][tid].x + b2.x;
                    r.y = s_part[0][tid].y + s_part[1][tid].y + s_part[2][tid].y + s_part[3][tid].y + b2.y;
                    ((float2*)s_ns[j])[tid] = r;
                    ((float2*)(g_hist + ((size_t)nd*HISTN + hsl)*HH))[tid] = r;
                }
                if (tid == TPB-1) s_cnt[nd] = cnt + 1;
                __syncthreads();
            }

            /* batched Wm + publish */
            {
                const __half2* W = (const __half2*)g_wm_h;
                const float* xs[CHB-1];
                #pragma unroll
                for (int b = 0; b < CHB-1; ++b)
                    xs[b] = (g2 < 2) ? (s_ns[b+1] + g2*128) : (s_msg[b+1] + (g2-2)*128);
                float2 acc[CHB-1];
                #pragma unroll
                for (int b = 0; b < CHB-1; ++b) acc[b] = make_float2(0.f, 0.f);
                const int r0 = g2*128;
                #pragma unroll 4
                for (int i = 0; i < 128; ++i) {
                    float2 w = __half22float2(W[(r0+i)*128 + c]);
                    #pragma unroll
                    for (int b = 0; b < CHB-1; ++b) {
                        float x = xs[b][i];
                        acc[b].x += x*w.x; acc[b].y += x*w.y;
                    }
                }
                #pragma unroll
                for (int b = 0; b < CHB-1; ++b) s_part[b*4 + g2][c] = acc[b];
            }
            __syncthreads();
            if (tid < 128) {
                float2 b2 = ((const float2*)bm)[tid];
                for (int b = 1; b < B; ++b) {
                    float2 r;
                    r.x = s_part[(b-1)*4+0][tid].x + s_part[(b-1)*4+1][tid].x
                        + s_part[(b-1)*4+2][tid].x + s_part[(b-1)*4+3][tid].x + b2.x;
                    r.y = s_part[(b-1)*4+0][tid].y + s_part[(b-1)*4+1][tid].y
                        + s_part[(b-1)*4+2][tid].y + s_part[(b-1)*4+3][tid].y + b2.y;
                    ((float2*)(g_msgs + (size_t)s_cs[b]*MM))[tid] = r;
                }
            }
            __syncthreads();
            if (tid == 0) {
                __threadfence();
                for (int b = 1; b < B; ++b) st_rel(&g_done_msg[s_cs[b]], 1);
            }
        }
        pos += B;
        __syncthreads();
    }
}

/* ---------------- K5: decoder + log_softmax ------------------------------- */
__global__ void k_out(const float* __restrict__ Wd, const float* __restrict__ bd,
                      float* __restrict__ out)
{
    __shared__ float s_fin[HH];
    __shared__ float s_log[PPV*OO];
    int n = blockIdx.x, t = threadIdx.x;     /* 128 threads */
    int cnt  = g_count[n];
    int slot = (cnt - 1) % HISTN;
    s_fin[t]       = g_hist[((size_t)n*HISTN + slot)*HH + t];
    s_fin[t + 128] = g_hist[((size_t)n*HISTN + slot)*HH + t + 128];
    __syncthreads();
    int p = t >> 6, o = t & 63;
    float acc = bd[p*OO + o];
    #pragma unroll 4
    for (int h = 0; h < HH; ++h) acc += s_fin[h]*Wd[((size_t)p*HH + h)*OO + o];
    s_log[t] = acc;
    __syncthreads();
    float m = -1e30f;
    for (int k = 0; k < OO; ++k) m = fmaxf(m, s_log[p*OO + k]);
    float sum = 0.f;
    for (int k = 0; k < OO; ++k) sum += expf(s_log[p*OO + k] - m);
    out[((size_t)p*NN + n)*OO + o] = acc - m - logf(sum);
}

/* -------------------------------------------------------------------------- */
extern "C" void kernel_launch(void* const* d_in, const int* in_sizes, int n_in,
                              void* d_out, int out_size)
{
    const float* xa  = (const float*)d_in[0];
    const int*   nbr = (const int*)  d_in[1];
    const float* fm  = (const float*)d_in[2];
    const float* We  = (const float*)d_in[3];
    const float* be  = (const float*)d_in[4];
    const float* Wq  = (const float*)d_in[5];
    const float* bq  = (const float*)d_in[6];
    const float* Wk  = (const float*)d_in[7];
    /* d_in[8] = bk cancels in softmax */
    const float* Wr  = (const float*)d_in[9];
    const float* br  = (const float*)d_in[10];
    const float* Wm  = (const float*)d_in[11];
    const float* bm  = (const float*)d_in[12];
    const float* Wd  = (const float*)d_in[13];
    const float* bd  = (const float*)d_in[14];
    const int*   nS  = (const int*)  d_in[15];

    k_encode<<<NN, HH>>>(xa, We, be);
    k_wrsum <<<HH, HH>>>(Wr);
    k_wmh   <<<2*HH, MM>>>(Wm);
    {
        dim3 g(8, 8), b(32, 32);
        k_prec<<<g, b>>>(Wq, Wk);
    }
    k_bqk   <<<8, 256>>>(Wk, bq);
    k_graph <<<1, TPB>>>(nbr, nS);
    k_main  <<<NB, TPB>>>(fm, br, bm, nS);
    k_out   <<<NN, 128>>>(Wd, bd, (float*)d_out);
}

// round 9
// speedup vs baseline: 3.2094x; 1.5897x over previous
#include <cuda_runtime.h>
#include <cuda_fp16.h>
#include <mma.h>
#include <math.h>

using namespace nvcuda;

#define NN    512
#define FF    128
#define HH    256
#define MM    256
#define DEGN  8
#define HISTN 10
#define OO    64
#define PPV   2
#define MAXS  (10*NN)     /* 5120 */
#define NLVL  6           /* level count upper bound (S>=1) */
#define BM    64
#define BN    64
#define BK    16

/* -------- persistent scratch (device globals; no allocation allowed) ------ */
__device__ float g_hist [NN*HISTN*HH];                    // node state rings (fp32)
__device__ float g_kq   [MAXS*HH];                        // per-step kq (fp32)
__device__ float g_w2   [MAXS*HH];                        // per-step msg@Wm2+bm (fp32)
__device__ __align__(16) __half g_msg_h[MAXS*HH];         // per-step out message (fp16)
__device__ __align__(16) __half g_ns_h [MAXS*HH];         // per-step new state (fp16)
__device__ __align__(16) __half g_fm_h [NN*MM];           // first_message (fp16)
__device__ __align__(16) __half g_B1   [HH*512];          // [A | Wm2] fp16, row k, 512 cols
__device__ __align__(16) __half g_B2   [HH*HH];           // Wm1 fp16
__device__ __align__(16) __half g_wr_h [HH*HH];           // Wr_sum fp16
__device__ float g_bias [512];                            // [bqk | bm]
__device__ float g_bqk  [HH];
__device__ int   g_bucket[MAXS];                          // steps grouped by node, sorted
__device__ int   g_boff  [NN+1];
__device__ int   g_count [NN];

/* ---- level bounds: level l covers steps [lo, hi), lo/hi from S ----------- */
__device__ __forceinline__ void level_bounds(int S, int level, int* plo, int* phi)
{
    int lo = 0, hi = (S < MAXS) ? S : MAXS;
    for (int l = 0; l < level; ++l) {
        lo = hi;
        int h2 = S + 8*hi;
        hi = (h2 > MAXS) ? MAXS : h2;
    }
    *plo = lo; *phi = hi;
}

/* ---------------- K1: encode xa -> hist slot0 ----------------------------- */
__global__ void k_encode(const float* __restrict__ xa, const float* __restrict__ We,
                         const float* __restrict__ be)
{
    __shared__ float sx[FF];
    int n = blockIdx.x, t = threadIdx.x;
    if (t < FF) sx[t] = xa[n*FF + t];
    __syncthreads();
    float acc = be[t];
    #pragma unroll 4
    for (int f = 0; f < FF; ++f) acc += sx[f] * We[f*HH + t];
    g_hist[((size_t)n*HISTN + 0)*HH + t] = acc;
    if (t == 0) g_count[n] = 1;
}

/* ---------------- K2: Wr_sum (fp16) --------------------------------------- */
__global__ void k_wrsum(const float* __restrict__ Wr)
{
    int i = blockIdx.x, t = threadIdx.x;
    float s = Wr[i*HH + t] + Wr[(HH + i)*HH + t]
            + Wr[(2*HH + i)*HH + t] + Wr[(3*HH + i)*HH + t];
    g_wr_h[i*HH + t] = __float2half(s);
}

/* ---------------- K2b: A = Wq @ Wk^T -> g_B1 cols 0..255 ------------------ */
__global__ void k_prec(const float* __restrict__ Wq, const float* __restrict__ Wk)
{
    __shared__ float a[32][33], bt[32][33];
    int tx = threadIdx.x, ty = threadIdx.y;
    int m0 = blockIdx.y*32, i0 = blockIdx.x*32;
    float acc = 0.f;
    for (int kt = 0; kt < HH; kt += 32) {
        a [ty][tx] = Wq[(m0+ty)*HH + kt + tx];
        bt[tx][ty] = Wk[(i0+ty)*HH + kt + tx];
        __syncthreads();
        #pragma unroll
        for (int k = 0; k < 32; ++k) acc += a[ty][k]*bt[k][tx];
        __syncthreads();
    }
    g_B1[(size_t)(m0+ty)*512 + i0 + tx] = __float2half(acc);
}

/* ---------------- K2c: bqk = Wk @ bq -------------------------------------- */
__global__ void k_bqk(const float* __restrict__ Wk, const float* __restrict__ bq)
{
    int w = threadIdx.x >> 5, l = threadIdx.x & 31;
    int r = blockIdx.x*8 + w;
    float p = 0.f;
    #pragma unroll
    for (int k = 0; k < 8; ++k) { int h = l + k*32; p += Wk[r*HH + h]*bq[h]; }
    #pragma unroll
    for (int o = 16; o > 0; o >>= 1) p += __shfl_down_sync(0xffffffffu, p, o);
    if (l == 0) g_bqk[r] = p;
}

/* -------- K2d: pack Wm halves + bias -------------------------------------- */
__global__ void k_wb(const float* __restrict__ Wm, const float* __restrict__ bm)
{
    int k = blockIdx.x, t = threadIdx.x;     /* 256 x 256 */
    g_B1[(size_t)k*512 + 256 + t] = __float2half(Wm[(size_t)(256+k)*MM + t]);
    g_B2[(size_t)k*256 + t]       = __float2half(Wm[(size_t)k*MM + t]);
    if (k == 0) {
        g_bias[t]       = g_bqk[t];
        g_bias[256 + t] = bm[t];
    }
}

/* -------- K2e: first_message -> fp16 -------------------------------------- */
__global__ void k_fmh(const float* __restrict__ fm)
{
    int n = blockIdx.x, t = threadIdx.x;
    g_fm_h[(size_t)n*MM + t] = __float2half(fm[(size_t)n*MM + t]);
}

/* ------- K3: node sequence + per-node sorted step buckets ----------------- */
__global__ void k_graph(const int* __restrict__ neighbors, const int* __restrict__ ns_ptr)
{
    __shared__ int sn[MAXS];   // 20 KB
    __shared__ int T[NN], P[NN], cur[NN];
    int t = threadIdx.x;       // 512 threads
    int S = *ns_ptr;
    for (int e = t; e < S && e < MAXS; e += 512) sn[e] = e;
    __syncthreads();
    int known = (S < MAXS) ? S : MAXS;
    while (known < MAXS) {
        long long nx = (long long)S + 8LL*(long long)known;
        int next = (nx > MAXS) ? MAXS : (int)nx;
        for (int e = known + t; e < next; e += 512) {
            int src = (e - S) >> 3;
            sn[e] = neighbors[sn[src]*DEGN + ((e - S) & 7)];
        }
        __syncthreads();
        known = next;
    }
    T[t] = 0; cur[t] = 0;
    __syncthreads();
    for (int e = t; e < MAXS; e += 512) atomicAdd(&T[sn[e]], 1);
    __syncthreads();
    P[t] = T[t];
    __syncthreads();
    for (int o = 1; o < NN; o <<= 1) {
        int v = (t >= o) ? P[t-o] : 0;
        __syncthreads();
        P[t] += v;
        __syncthreads();
    }
    g_boff[t] = P[t] - T[t];
    if (t == NN-1) g_boff[NN] = P[t];
    __syncthreads();
    for (int e = t; e < MAXS; e += 512) {
        int nd = sn[e];
        int pos = atomicAdd(&cur[nd], 1);
        g_bucket[(P[nd] - T[nd]) + pos] = e;
    }
    __syncthreads();
    {   /* insertion-sort own bucket (<= ~30 entries) */
        int b0 = P[t] - T[t], b1 = P[t];
        for (int i = b0 + 1; i < b1; ++i) {
            int v = g_bucket[i], j = i - 1;
            while (j >= b0 && g_bucket[j] > v) { g_bucket[j+1] = g_bucket[j]; --j; }
            g_bucket[j+1] = v;
        }
    }
}

/* ------- GEMM1 (wmma): [KQ | W2] = msg_src @ [A | Wm2] + [bqk | bm] ------- */
__global__ void __launch_bounds__(256) k_gemm1(int level, const int* __restrict__ ns_ptr)
{
    int S = *ns_ptr, lo, hi;
    level_bounds(S, level, &lo, &hi);
    if (lo >= hi) return;
    const int M = hi - lo;
    const int m0 = blockIdx.x * BM;
    if (m0 >= M) return;
    const int n0 = blockIdx.y * BN;

    __shared__ __half sA[BM][BK];
    __shared__ __half sB[BK][BN];
    __shared__ float  sO[BM][BN];

    const int tid = threadIdx.x;
    const int wid = tid >> 5;
    const int wr = wid & 3, wc = wid >> 2;
    wmma::fragment<wmma::accumulator,16,16,16,float> acc[2];
    wmma::fill_fragment(acc[0], 0.f);
    wmma::fill_fragment(acc[1], 0.f);

    const int ar = tid >> 2, ac = (tid & 3) * 4;        /* A tile: 64 x 16 */
    const int brw = tid >> 4, bc = (tid & 15) * 4;      /* B tile: 16 x 64 */
    const int s = lo + m0 + ar;
    const __half* ap = 0;
    if (s < hi) ap = (s < S) ? (g_fm_h + (size_t)s*MM)
                             : (g_msg_h + (size_t)((s - S) >> 3)*MM);
    for (int kt = 0; kt < HH; kt += BK) {
        if (ap) *(uint2*)&sA[ar][ac] = *(const uint2*)(ap + kt + ac);
        else    *(uint2*)&sA[ar][ac] = make_uint2(0u, 0u);
        *(uint2*)&sB[brw][bc] = *(const uint2*)(g_B1 + (size_t)(kt + brw)*512 + n0 + bc);
        __syncthreads();
        wmma::fragment<wmma::matrix_a,16,16,16,__half,wmma::row_major> fa;
        wmma::load_matrix_sync(fa, &sA[wr*16][0], BK);
        #pragma unroll
        for (int j = 0; j < 2; ++j) {
            wmma::fragment<wmma::matrix_b,16,16,16,__half,wmma::row_major> fb;
            wmma::load_matrix_sync(fb, &sB[0][wc*32 + j*16], BN);
            wmma::mma_sync(acc[j], fa, fb, acc[j]);
        }
        __syncthreads();
    }
    wmma::store_matrix_sync(&sO[wr*16][wc*32],      acc[0], BN, wmma::mem_row_major);
    wmma::store_matrix_sync(&sO[wr*16][wc*32 + 16], acc[1], BN, wmma::mem_row_major);
    __syncthreads();
    for (int idx = tid; idx < BM*BN; idx += 256) {
        int r = idx >> 6, nl = idx & 63;
        int ss = lo + m0 + r;
        if (ss < hi) {
            int n = n0 + nl;
            float v = sO[r][nl] + g_bias[n];
            if (n < HH) g_kq[(size_t)ss*HH + n] = v;
            else        g_w2[(size_t)ss*HH + (n - HH)] = v;
        }
    }
}

/* ------- GEMM2 (wmma): msg = NS @ Wm1 + W2 -> fp16 ------------------------ */
__global__ void __launch_bounds__(256) k_gemm2(int level, const int* __restrict__ ns_ptr)
{
    int S = *ns_ptr, lo, hi;
    level_bounds(S, level, &lo, &hi);
    if (lo >= hi) return;
    const int M = hi - lo;
    const int m0 = blockIdx.x * BM;
    if (m0 >= M) return;
    const int n0 = blockIdx.y * BN;

    __shared__ __half sA[BM][BK];
    __shared__ __half sB[BK][BN];
    __shared__ float  sO[BM][BN];

    const int tid = threadIdx.x;
    const int wid = tid >> 5;
    const int wr = wid & 3, wc = wid >> 2;
    wmma::fragment<wmma::accumulator,16,16,16,float> acc[2];
    wmma::fill_fragment(acc[0], 0.f);
    wmma::fill_fragment(acc[1], 0.f);

    const int ar = tid >> 2, ac = (tid & 3) * 4;
    const int brw = tid >> 4, bc = (tid & 15) * 4;
    const int s = lo + m0 + ar;
    for (int kt = 0; kt < HH; kt += BK) {
        if (s < hi) *(uint2*)&sA[ar][ac] = *(const uint2*)(g_ns_h + (size_t)s*HH + kt + ac);
        else        *(uint2*)&sA[ar][ac] = make_uint2(0u, 0u);
        *(uint2*)&sB[brw][bc] = *(const uint2*)(g_B2 + (size_t)(kt + brw)*256 + n0 + bc);
        __syncthreads();
        wmma::fragment<wmma::matrix_a,16,16,16,__half,wmma::row_major> fa;
        wmma::load_matrix_sync(fa, &sA[wr*16][0], BK);
        #pragma unroll
        for (int j = 0; j < 2; ++j) {
            wmma::fragment<wmma::matrix_b,16,16,16,__half,wmma::row_major> fb;
            wmma::load_matrix_sync(fb, &sB[0][wc*32 + j*16], BN);
            wmma::mma_sync(acc[j], fa, fb, acc[j]);
        }
        __syncthreads();
    }
    wmma::store_matrix_sync(&sO[wr*16][wc*32],      acc[0], BN, wmma::mem_row_major);
    wmma::store_matrix_sync(&sO[wr*16][wc*32 + 16], acc[1], BN, wmma::mem_row_major);
    __syncthreads();
    for (int idx = tid; idx < BM*BN; idx += 256) {
        int r = idx >> 6, nl = idx & 63;
        int ss = lo + m0 + r;
        if (ss < hi) {
            int n = n0 + nl;
            float v = sO[r][nl] + g_w2[(size_t)ss*HH + n];
            g_msg_h[(size_t)ss*HH + n] = __float2half(v);
        }
    }
}

/* ------- SEQ: per-node sequential chain within a level -------------------- */
__global__ void __launch_bounds__(256) k_seq(int level, const int* __restrict__ ns_ptr,
                                             const float* __restrict__ br)
{
    __shared__ float  s_kq[HH];
    __shared__ float2 s_part[2][128];
    __shared__ float  s_vals[HH];
    __shared__ float  s_logit[16], s_attn[HISTN];
    __shared__ int    s_i0, s_i1, s_cnt;

    int S = *ns_ptr, lo, hi;
    level_bounds(S, level, &lo, &hi);
    if (lo >= hi) return;
    const int nd = blockIdx.x;
    const int tid = threadIdx.x;
    if (tid == 0) {
        int b0 = g_boff[nd], b1 = g_boff[nd+1];
        int i0 = b0; while (i0 < b1 && g_bucket[i0] < lo) ++i0;
        int i1 = i0; while (i1 < b1 && g_bucket[i1] < hi) ++i1;
        s_i0 = i0; s_i1 = i1; s_cnt = g_count[nd];
    }
    __syncthreads();
    const int i0 = s_i0, i1 = s_i1;
    if (i0 >= i1) return;
    int cnt = s_cnt;
    const int wid = tid >> 5, lid = tid & 31;
    const int g = tid >> 7, c = tid & 127;

    for (int i = i0; i < i1; ++i) {
        const int sstep = g_bucket[i];
        s_kq[tid] = g_kq[(size_t)sstep*HH + tid];
        __syncthreads();
        const int nv   = (cnt < HISTN) ? cnt : HISTN;
        const int slot = cnt % HISTN;
        /* logits: warp per hist slot, 2 passes */
        #pragma unroll
        for (int pass = 0; pass < 2; ++pass) {
            int sl = wid + pass*8;
            if (sl < nv) {
                const float* hp = g_hist + ((size_t)nd*HISTN + sl)*HH;
                float p = 0.f;
                #pragma unroll
                for (int k = 0; k < 8; ++k) { int h = lid + k*32; p += hp[h]*s_kq[h]; }
                #pragma unroll
                for (int o = 16; o > 0; o >>= 1) p += __shfl_down_sync(0xffffffffu, p, o);
                if (lid == 0) s_logit[sl] = p * 0.0625f;   /* 1/sqrt(256) */
            }
        }
        __syncthreads();
        if (tid == 0) {
            float m = -1e30f;
            for (int k = 0; k < nv; ++k) m = fmaxf(m, s_logit[k]);
            float sum = 0.f;
            for (int k = 0; k < nv; ++k) { float e = __expf(s_logit[k]-m); s_attn[k]=e; sum+=e; }
            float inv = 1.f / sum;
            for (int k = 0; k < nv; ++k) s_attn[k] *= inv;
        }
        __syncthreads();
        {
            float v = 0.f;
            const float* hp = g_hist + (size_t)nd*HISTN*HH + tid;
            #pragma unroll 2
            for (int k = 0; k < nv; ++k) v += s_attn[k]*hp[k*HH];
            s_vals[tid] = v;
        }
        __syncthreads();
        /* ns = vals @ Wr_sum + br */
        {
            const __half2* W = (const __half2*)g_wr_h;
            float2 a = make_float2(0.f, 0.f);
            const int r0 = g*128;
            #pragma unroll 8
            for (int r = r0; r < r0+128; ++r) {
                float x = s_vals[r];
                float2 w = __half22float2(W[(size_t)r*128 + c]);
                a.x += x*w.x; a.y += x*w.y;
            }
            s_part[g][c] = a;
        }
        __syncthreads();
        if (tid < 128) {
            float2 b2 = ((const float2*)br)[tid];
            float2 r;
            r.x = s_part[0][tid].x + s_part[1][tid].x + b2.x;
            r.y = s_part[0][tid].y + s_part[1][tid].y + b2.y;
            ((float2*)(g_hist + ((size_t)nd*HISTN + slot)*HH))[tid] = r;
            ((half2*)(g_ns_h + (size_t)sstep*HH))[tid] = __float22half2_rn(r);
        }
        ++cnt;
        __syncthreads();
    }
    if (tid == 0) g_count[nd] = cnt;
}

/* ---------------- K5: decoder + log_softmax ------------------------------- */
__global__ void k_out(const float* __restrict__ Wd, const float* __restrict__ bd,
                      float* __restrict__ out)
{
    __shared__ float s_fin[HH];
    __shared__ float s_log[PPV*OO];
    int n = blockIdx.x, t = threadIdx.x;     /* 128 threads */
    int cnt  = g_count[n];
    int slot = (cnt - 1) % HISTN;
    s_fin[t]       = g_hist[((size_t)n*HISTN + slot)*HH + t];
    s_fin[t + 128] = g_hist[((size_t)n*HISTN + slot)*HH + t + 128];
    __syncthreads();
    int p = t >> 6, o = t & 63;
    float acc = bd[p*OO + o];
    #pragma unroll 4
    for (int h = 0; h < HH; ++h) acc += s_fin[h]*Wd[((size_t)p*HH + h)*OO + o];
    s_log[t] = acc;
    __syncthreads();
    float m = -1e30f;
    for (int k = 0; k < OO; ++k) m = fmaxf(m, s_log[p*OO + k]);
    float sum = 0.f;
    for (int k = 0; k < OO; ++k) sum += expf(s_log[p*OO + k] - m);
    out[((size_t)p*NN + n)*OO + o] = acc - m - logf(sum);
}

/* -------------------------------------------------------------------------- */
extern "C" void kernel_launch(void* const* d_in, const int* in_sizes, int n_in,
                              void* d_out, int out_size)
{
    const float* xa  = (const float*)d_in[0];
    const int*   nbr = (const int*)  d_in[1];
    const float* fm  = (const float*)d_in[2];
    const float* We  = (const float*)d_in[3];
    const float* be  = (const float*)d_in[4];
    const float* Wq  = (const float*)d_in[5];
    const float* bq  = (const float*)d_in[6];
    const float* Wk  = (const float*)d_in[7];
    /* d_in[8] = bk cancels in softmax */
    const float* Wr  = (const float*)d_in[9];
    const float* br  = (const float*)d_in[10];
    const float* Wm  = (const float*)d_in[11];
    const float* bm  = (const float*)d_in[12];
    const float* Wd  = (const float*)d_in[13];
    const float* bd  = (const float*)d_in[14];
    const int*   nS  = (const int*)  d_in[15];

    k_encode<<<NN, HH>>>(xa, We, be);
    k_wrsum <<<HH, HH>>>(Wr);
    {
        dim3 g(8, 8), b(32, 32);
        k_prec<<<g, b>>>(Wq, Wk);
    }
    k_bqk   <<<8, 256>>>(Wk, bq);
    k_wb    <<<256, 256>>>(Wm, bm);
    k_fmh   <<<NN, 256>>>(fm);
    k_graph <<<1, 512>>>(nbr, nS);

    for (int lvl = 0; lvl < NLVL; ++lvl) {
        k_gemm1<<<dim3(MAXS/BM, 512/BN), 256>>>(lvl, nS);
        k_seq  <<<NN, 256>>>(lvl, nS, br);
        k_gemm2<<<dim3(MAXS/BM, 256/BN), 256>>>(lvl, nS);
    }
    k_out<<<NN, 128>>>(Wd, bd, (float*)d_out);
}